// round 2
// baseline (speedup 1.0000x reference)
#include <cuda_runtime.h>
#include <cstdint>

#define B 256
#define L 128
#define F 256
#define S 512
#define BF (B*F)
#define G4F 1024

// ---- static device scratch (no allocation) ----
__device__ float    g_Wc[G4F * F];     // combined W_ih+W_hh, permuted [nf*128+c][k], tf32-rounded
__device__ float    g_WihT[G4F * F];   // [(nf*256+k)*128 + c]
__device__ float    g_WhhT[G4F * F];
__device__ float    g_WiT[L * F];      // [k*256 + f]
__device__ float    g_bc[G4F];         // permuted combined bias
__device__ float    g_init[B * F];
__device__ float    g_c1[B * F];
__device__ unsigned g_bar[8 * 512];    // per-group per-step counters

__device__ __forceinline__ float sigf(float x) { return 1.0f / (1.0f + expf(-x)); }

__global__ void reset_kernel() {
    g_bar[blockIdx.x * blockDim.x + threadIdx.x] = 0u;
}

// ---- P0: weight prep ----
__global__ void prep_kernel(const float* __restrict__ Wih, const float* __restrict__ Whh,
                            const float* __restrict__ bih, const float* __restrict__ bhh,
                            const float* __restrict__ Wi) {
    int bid = blockIdx.x, tid = threadIdx.x;
    if (bid < 1024) {
        int r = bid, k = tid;
        int g = r >> 8;          // gate 0..3 (i,f,g,o)
        int jj = r & 255;        // feature
        int nf = jj >> 5;        // slice
        int j  = jj & 31;
        int c  = g * 32 + j;     // permuted column within slice
        float wih = Wih[r * 256 + k];
        float whh = Whh[r * 256 + k];
        float s = wih + whh;
        unsigned us;
        asm("cvt.rna.tf32.f32 %0, %1;" : "=r"(us) : "f"(s));
        g_Wc[(nf * 128 + c) * 256 + k] = __uint_as_float(us);
        g_WihT[(nf * 256 + k) * 128 + c] = wih;
        g_WhhT[(nf * 256 + k) * 128 + c] = whh;
        if (k == 0) g_bc[nf * 128 + c] = bih[r] + bhh[r];
    } else {
        int k = bid - 1024;      // 0..127
        int f = tid;             // 0..255
        g_WiT[k * 256 + f] = Wi[f * 128 + k];
    }
}

// ---- P1: init = elu(x @ Wi.T + bi), fp32 ----
__global__ void init_kernel(const float* __restrict__ x, const float* __restrict__ bi) {
    __shared__ float xs[32 * 128];
    int bid = blockIdx.x, tid = threadIdx.x;
    int bt = bid >> 2, ft = bid & 3;
    for (int i = tid; i < 32 * 128; i += 256)
        xs[i] = x[(bt * 32 + (i >> 7)) * 128 + (i & 127)];
    __syncthreads();
    int tx = tid & 15, ty = tid >> 4;
    int b0 = ty * 2;
    int f0 = ft * 64 + tx * 4;
    float acc[2][4] = {};
#pragma unroll 4
    for (int k = 0; k < 128; ++k) {
        float4 w = *(const float4*)&g_WiT[k * 256 + f0];
        float x0 = xs[b0 * 128 + k];
        float x1 = xs[(b0 + 1) * 128 + k];
        acc[0][0] += x0 * w.x; acc[0][1] += x0 * w.y; acc[0][2] += x0 * w.z; acc[0][3] += x0 * w.w;
        acc[1][0] += x1 * w.x; acc[1][1] += x1 * w.y; acc[1][2] += x1 * w.z; acc[1][3] += x1 * w.w;
    }
#pragma unroll
    for (int r = 0; r < 2; ++r)
#pragma unroll
        for (int cc = 0; cc < 4; ++cc) {
            float v = acc[r][cc] + bi[f0 + cc];
            v = (v > 0.0f) ? v : expm1f(v);
            g_init[(bt * 32 + b0 + r) * 256 + f0 + cc] = v;
        }
}

// ---- P2: step 0 (inp = last_feat, h = c = init), fp32, writes d_out row 0 + g_c1 ----
__global__ void step0_kernel(const float* __restrict__ lf, float* __restrict__ d_out) {
    extern __shared__ float sm[];
    float* lfs = sm;
    float* ins = sm + 32 * 256;
    int bid = blockIdx.x, tid = threadIdx.x;
    int nf = bid & 7, mbt = bid >> 3;
    for (int i = tid; i < 32 * 256; i += 256) {
        int gi = (mbt * 32 + (i >> 8)) * 256 + (i & 255);
        lfs[i] = lf[gi];
        ins[i] = g_init[gi];
    }
    __syncthreads();
    int tx = tid & 31, ty = tid >> 5;
    int c0 = tx * 4;
    float acc[4][4] = {};
#pragma unroll 2
    for (int k = 0; k < 256; ++k) {
        float4 wih = *(const float4*)&g_WihT[(nf * 256 + k) * 128 + c0];
        float4 whh = *(const float4*)&g_WhhT[(nf * 256 + k) * 128 + c0];
#pragma unroll
        for (int e = 0; e < 4; ++e) {
            int b = ty + 8 * e;
            float lv = lfs[b * 256 + k];
            float iv = ins[b * 256 + k];
            acc[e][0] += lv * wih.x + iv * whh.x;
            acc[e][1] += lv * wih.y + iv * whh.y;
            acc[e][2] += lv * wih.z + iv * whh.z;
            acc[e][3] += lv * wih.w + iv * whh.w;
        }
    }
    __syncthreads();
    float* gss = lfs;  // overlay (lfs dead), stride 132
#pragma unroll
    for (int e = 0; e < 4; ++e)
#pragma unroll
        for (int cc = 0; cc < 4; ++cc)
            gss[(ty + 8 * e) * 132 + c0 + cc] = acc[e][cc];
    __syncthreads();
#pragma unroll
    for (int e = 0; e < 4; ++e) {
        int li = tid + 256 * e;
        int b = li >> 5, j = li & 31;
        float iv = gss[b * 132 + j]      + g_bc[nf * 128 + j];
        float fv = gss[b * 132 + 32 + j] + g_bc[nf * 128 + 32 + j];
        float gv = gss[b * 132 + 64 + j] + g_bc[nf * 128 + 64 + j];
        float ov = gss[b * 132 + 96 + j] + g_bc[nf * 128 + 96 + j];
        float cp = ins[b * 256 + nf * 32 + j];
        float cn = sigf(fv) * cp + sigf(iv) * tanhf(gv);
        float hn = sigf(ov) * tanhf(cn);
        int gi = (mbt * 32 + b) * 256 + nf * 32 + j;
        g_c1[gi] = cn;
        d_out[gi] = hn;   // outs[0] = h_1
    }
}

// ---- tf32 mma helper ----
__device__ __forceinline__ void mma8(float* d, const unsigned* a, unsigned b0, unsigned b1) {
    asm volatile(
        "mma.sync.aligned.m16n8k8.row.col.f32.tf32.tf32.f32 "
        "{%0,%1,%2,%3}, {%4,%5,%6,%7}, {%8,%9}, {%0,%1,%2,%3};"
        : "+f"(d[0]), "+f"(d[1]), "+f"(d[2]), "+f"(d[3])
        : "r"(a[0]), "r"(a[1]), "r"(a[2]), "r"(a[3]), "r"(b0), "r"(b1));
}

// ---- P3: persistent recurrence, steps t = 1..511 ----
// 64 CTAs x 128 threads. nf = bid&7 (128 gate cols), mb = bid>>3 (32 batch rows).
__global__ void __launch_bounds__(128, 1)
lstm_kernel(float* __restrict__ d_out) {
    extern __shared__ float sm[];
    float* ws  = sm;                       // 128*260
    float* hs  = ws + 128 * 260;           // 32*260
    float* gs  = hs + 32 * 260;            // 32*132
    float* bcs = gs + 32 * 132;            // 128

    int tid = threadIdx.x;
    int nf = blockIdx.x & 7, mb = blockIdx.x >> 3;

    for (int i = tid; i < 128 * 256; i += 128) {
        int c = i >> 8, k = i & 255;
        ws[c * 260 + k] = g_Wc[(nf * 128 + c) * 256 + k];
    }
    bcs[tid] = g_bc[nf * 128 + tid];

    float creg[8];
#pragma unroll
    for (int e = 0; e < 8; ++e) {
        int li = e * 128 + tid;
        creg[e] = g_c1[(mb * 32 + (li >> 5)) * 256 + nf * 32 + (li & 31)];
    }

    int warp = tid >> 5, lane = tid & 31;
    int gID = lane >> 2, tig = lane & 3;
    unsigned* bar = &g_bar[mb * 512];
    __syncthreads();

    for (int t = 1; t < 512; ++t) {
        // wait for all 8 CTAs of this group to have written h_t (t>=2; t==1 by stream order)
        if (tid == 0 && t >= 2) {
            volatile unsigned* p = bar + (t - 1);
            while (*p < 8u) { }
            __threadfence();
        }
        __syncthreads();   // also protects hs/gs reuse across iterations

        // load h_t (32 x 256) -> smem, round to tf32
        const float* hsrc = d_out + (size_t)(t - 1) * BF + (size_t)mb * 32 * 256;
        for (int i = tid * 4; i < 8192; i += 512) {
            float4 v = *(const float4*)(hsrc + i);
            unsigned u0, u1, u2, u3;
            asm("cvt.rna.tf32.f32 %0, %1;" : "=r"(u0) : "f"(v.x));
            asm("cvt.rna.tf32.f32 %0, %1;" : "=r"(u1) : "f"(v.y));
            asm("cvt.rna.tf32.f32 %0, %1;" : "=r"(u2) : "f"(v.z));
            asm("cvt.rna.tf32.f32 %0, %1;" : "=r"(u3) : "f"(v.w));
            v.x = __uint_as_float(u0); v.y = __uint_as_float(u1);
            v.z = __uint_as_float(u2); v.w = __uint_as_float(u3);
            *(float4*)&hs[(i >> 8) * 260 + (i & 255)] = v;
        }
        __syncthreads();

        // gates (32 x 128) = hs @ ws^T via tf32 mma; warp covers 32 cols
        float acc[2][4][4];
#pragma unroll
        for (int mt = 0; mt < 2; ++mt)
#pragma unroll
            for (int nt = 0; nt < 4; ++nt)
#pragma unroll
                for (int q = 0; q < 4; ++q) acc[mt][nt][q] = 0.0f;

#pragma unroll 4
        for (int kb = 0; kb < 32; ++kb) {
            int k0 = kb * 8;
            unsigned a[2][4];
#pragma unroll
            for (int mt = 0; mt < 2; ++mt) {
                int r = mt * 16 + gID;
                a[mt][0] = __float_as_uint(hs[r * 260 + k0 + tig]);
                a[mt][1] = __float_as_uint(hs[(r + 8) * 260 + k0 + tig]);
                a[mt][2] = __float_as_uint(hs[r * 260 + k0 + 4 + tig]);
                a[mt][3] = __float_as_uint(hs[(r + 8) * 260 + k0 + 4 + tig]);
            }
#pragma unroll
            for (int nt = 0; nt < 4; ++nt) {
                int c = warp * 32 + nt * 8 + gID;
                unsigned b0 = __float_as_uint(ws[c * 260 + k0 + tig]);
                unsigned b1 = __float_as_uint(ws[c * 260 + k0 + 4 + tig]);
                mma8(acc[0][nt], a[0], b0, b1);
                mma8(acc[1][nt], a[1], b0, b1);
            }
        }

        // stage gates to smem for cross-warp elementwise
#pragma unroll
        for (int mt = 0; mt < 2; ++mt)
#pragma unroll
            for (int nt = 0; nt < 4; ++nt) {
                int r = mt * 16 + gID;
                int c = warp * 32 + nt * 8 + 2 * tig;
                *(float2*)&gs[r * 132 + c]       = make_float2(acc[mt][nt][0], acc[mt][nt][1]);
                *(float2*)&gs[(r + 8) * 132 + c] = make_float2(acc[mt][nt][2], acc[mt][nt][3]);
            }
        __syncthreads();

        // elementwise LSTM update + write h_{t+1}
        float* dst = d_out + (size_t)t * BF + (size_t)mb * 32 * 256;
#pragma unroll
        for (int e = 0; e < 8; ++e) {
            int li = e * 128 + tid;
            int b = li >> 5, j = li & 31;
            float iv = gs[b * 132 + j]      + bcs[j];
            float fv = gs[b * 132 + 32 + j] + bcs[32 + j];
            float gv = gs[b * 132 + 64 + j] + bcs[64 + j];
            float ov = gs[b * 132 + 96 + j] + bcs[96 + j];
            float cn = sigf(fv) * creg[e] + sigf(iv) * tanhf(gv);
            float hn = sigf(ov) * tanhf(cn);
            creg[e] = cn;
            dst[b * 256 + nf * 32 + j] = hn;
        }
        __threadfence();
        __syncthreads();
        if (tid == 0) atomicAdd(&bar[t], 1u);
    }
}

extern "C" void kernel_launch(void* const* d_in, const int* in_sizes, int n_in,
                              void* d_out, int out_size) {
    const float* x   = (const float*)d_in[0];
    const float* lf  = (const float*)d_in[1];
    const float* Wi  = (const float*)d_in[2];
    const float* bi  = (const float*)d_in[3];
    const float* Wih = (const float*)d_in[4];
    const float* Whh = (const float*)d_in[5];
    const float* bih = (const float*)d_in[6];
    const float* bhh = (const float*)d_in[7];
    float* out = (float*)d_out;

    cudaFuncSetAttribute(step0_kernel, cudaFuncAttributeMaxDynamicSharedMemorySize, 65536);
    cudaFuncSetAttribute(lstm_kernel,  cudaFuncAttributeMaxDynamicSharedMemorySize, 183808);

    reset_kernel<<<8, 512>>>();
    prep_kernel<<<1152, 256>>>(Wih, Whh, bih, bhh, Wi);
    init_kernel<<<32, 256>>>(x, bi);
    step0_kernel<<<64, 256, 65536>>>(lf, out);
    lstm_kernel<<<64, 128, 183808>>>(out);
}

// round 3
// speedup vs baseline: 2.9396x; 2.9396x over previous
#include <cuda_runtime.h>
#include <cstdint>

#define B 256
#define L 128
#define F 256
#define S 512
#define BF (B*F)
#define G4F 1024

// ---- static device scratch (no allocation) ----
__device__ float g_Wc[G4F * F];     // combined W_ih+W_hh, permuted [nf*128+c][k], tf32-rounded
__device__ float g_WihT[G4F * F];   // [(nf*256+k)*128 + c]  (permuted c)
__device__ float g_WhhT[G4F * F];
__device__ float g_WiT[L * F];      // [k*256 + f]
__device__ float g_bc[G4F];         // permuted combined bias
__device__ float g_init[B * F];
__device__ float g_c1[B * F];

__device__ __forceinline__ float sigf(float x) { return 1.0f / (1.0f + expf(-x)); }
__device__ __forceinline__ float tanhfast(float x) {
    float r; asm("tanh.approx.f32 %0, %1;" : "=f"(r) : "f"(x)); return r;
}
__device__ __forceinline__ float sigfast(float x) { return 0.5f * tanhfast(0.5f * x) + 0.5f; }

// ---- P0: weight prep ----
// col permutation within a 128-col slice: c = (j>>3)*32 + gate*8 + (j&7)
__global__ void prep_kernel(const float* __restrict__ Wih, const float* __restrict__ Whh,
                            const float* __restrict__ bih, const float* __restrict__ bhh,
                            const float* __restrict__ Wi) {
    int bid = blockIdx.x, tid = threadIdx.x;
    if (bid < 1024) {
        int r = bid, k = tid;
        int g = r >> 8;          // gate 0..3 (i,f,g,o)
        int jj = r & 255;        // feature
        int nf = jj >> 5;        // slice
        int j  = jj & 31;
        int c  = ((j >> 3) << 5) + (g << 3) + (j & 7);
        float wih = Wih[r * 256 + k];
        float whh = Whh[r * 256 + k];
        float s = wih + whh;
        unsigned us;
        asm("cvt.rna.tf32.f32 %0, %1;" : "=r"(us) : "f"(s));
        g_Wc[(nf * 128 + c) * 256 + k] = __uint_as_float(us);
        g_WihT[(nf * 256 + k) * 128 + c] = wih;
        g_WhhT[(nf * 256 + k) * 128 + c] = whh;
        if (k == 0) g_bc[nf * 128 + c] = bih[r] + bhh[r];
    } else {
        int k = bid - 1024;      // 0..127
        int f = tid;             // 0..255
        g_WiT[k * 256 + f] = Wi[f * 128 + k];
    }
}

// ---- P1: init = elu(x @ Wi.T + bi), fp32 ----
__global__ void init_kernel(const float* __restrict__ x, const float* __restrict__ bi) {
    __shared__ float xs[32 * 128];
    int bid = blockIdx.x, tid = threadIdx.x;
    int bt = bid >> 2, ft = bid & 3;
    for (int i = tid; i < 32 * 128; i += 256)
        xs[i] = x[(bt * 32 + (i >> 7)) * 128 + (i & 127)];
    __syncthreads();
    int tx = tid & 15, ty = tid >> 4;
    int b0 = ty * 2;
    int f0 = ft * 64 + tx * 4;
    float acc[2][4] = {};
#pragma unroll 4
    for (int k = 0; k < 128; ++k) {
        float4 w = *(const float4*)&g_WiT[k * 256 + f0];
        float x0 = xs[b0 * 128 + k];
        float x1 = xs[(b0 + 1) * 128 + k];
        acc[0][0] += x0 * w.x; acc[0][1] += x0 * w.y; acc[0][2] += x0 * w.z; acc[0][3] += x0 * w.w;
        acc[1][0] += x1 * w.x; acc[1][1] += x1 * w.y; acc[1][2] += x1 * w.z; acc[1][3] += x1 * w.w;
    }
#pragma unroll
    for (int r = 0; r < 2; ++r)
#pragma unroll
        for (int cc = 0; cc < 4; ++cc) {
            float v = acc[r][cc] + bi[f0 + cc];
            v = (v > 0.0f) ? v : expm1f(v);
            g_init[(bt * 32 + b0 + r) * 256 + f0 + cc] = v;
        }
}

// ---- P2: step 0 (inp = last_feat, h = c = init), fp32, SMEM-tiled weights ----
// grid 128: nf = bid&7, mbt = bid>>3 (16 batch rows). 256 threads.
// dyn smem: lfs[16*256] + ins[16*256] + wih[64*128] + whh[64*128] = 96 KB
__global__ void step0_kernel(const float* __restrict__ lf, float* __restrict__ d_out) {
    extern __shared__ float sm[];
    float* lfs = sm;                 // 4096
    float* ins = lfs + 16 * 256;     // 4096
    float* wih = ins + 16 * 256;     // 8192
    float* whh = wih + 64 * 128;     // 8192
    int tid = threadIdx.x;
    int nf = blockIdx.x & 7, mbt = blockIdx.x >> 3;
    for (int i = tid; i < 16 * 256; i += 256) {
        int gi = (mbt * 16 + (i >> 8)) * 256 + (i & 255);
        lfs[i] = lf[gi];
        ins[i] = g_init[gi];
    }
    int tx = tid & 31, ty = tid >> 5;
    int c0 = tx * 4;
    float acc[2][4] = {};
    for (int kc = 0; kc < 4; ++kc) {
        __syncthreads();
        for (int i = tid; i < 64 * 128; i += 256) {
            int k = kc * 64 + (i >> 7), c = i & 127;
            wih[i] = g_WihT[(nf * 256 + k) * 128 + c];
            whh[i] = g_WhhT[(nf * 256 + k) * 128 + c];
        }
        __syncthreads();
#pragma unroll 4
        for (int k = 0; k < 64; ++k) {
            float4 a4 = *(const float4*)&wih[k * 128 + c0];
            float4 b4 = *(const float4*)&whh[k * 128 + c0];
#pragma unroll
            for (int e = 0; e < 2; ++e) {
                int b = ty + 8 * e;
                float lv = lfs[b * 256 + kc * 64 + k];
                float iv = ins[b * 256 + kc * 64 + k];
                acc[e][0] += lv * a4.x + iv * b4.x;
                acc[e][1] += lv * a4.y + iv * b4.y;
                acc[e][2] += lv * a4.z + iv * b4.z;
                acc[e][3] += lv * a4.w + iv * b4.w;
            }
        }
    }
    __syncthreads();
    float* gss = lfs;  // overlay (lfs dead; ins still live), 16*132 = 2112 < 4096
#pragma unroll
    for (int e = 0; e < 2; ++e)
#pragma unroll
        for (int cc = 0; cc < 4; ++cc)
            gss[(ty + 8 * e) * 132 + c0 + cc] = acc[e][cc];
    __syncthreads();
#pragma unroll
    for (int e2 = 0; e2 < 2; ++e2) {
        int li = tid + 256 * e2;
        int b = li >> 5, j = li & 31;
        int cb = ((j >> 3) << 5) + (j & 7);   // gate 0 column; gates at +8,+16,+24
        float iv = gss[b * 132 + cb]      + g_bc[nf * 128 + cb];
        float fv = gss[b * 132 + cb + 8]  + g_bc[nf * 128 + cb + 8];
        float gv = gss[b * 132 + cb + 16] + g_bc[nf * 128 + cb + 16];
        float ov = gss[b * 132 + cb + 24] + g_bc[nf * 128 + cb + 24];
        float cp = ins[b * 256 + nf * 32 + j];
        float cn = sigf(fv) * cp + sigf(iv) * tanhf(gv);
        float hn = sigf(ov) * tanhf(cn);
        int gi = (mbt * 16 + b) * 256 + nf * 32 + j;
        g_c1[gi] = cn;
        d_out[gi] = hn;   // outs[0] = h_1
    }
}

// ---- tf32 mma helper ----
__device__ __forceinline__ void mma8(float* d, const unsigned* a, unsigned b0, unsigned b1) {
    asm volatile(
        "mma.sync.aligned.m16n8k8.row.col.f32.tf32.tf32.f32 "
        "{%0,%1,%2,%3}, {%4,%5,%6,%7}, {%8,%9}, {%0,%1,%2,%3};"
        : "+f"(d[0]), "+f"(d[1]), "+f"(d[2]), "+f"(d[3])
        : "r"(a[0]), "r"(a[1]), "r"(a[2]), "r"(a[3]), "r"(b0), "r"(b1));
}

// ---- P3: persistent recurrence, steps t = 1..511, 8-CTA clusters ----
// 64 CTAs x 128 threads. Cluster = batch group (mb = bid>>3); nf = bid&7.
__global__ void __cluster_dims__(8, 1, 1) __launch_bounds__(128, 1)
lstm_kernel(float* __restrict__ d_out) {
    extern __shared__ float sm[];
    float* ws = sm;                  // 128*260
    float* hs = ws + 128 * 260;      // 32*260

    int tid = threadIdx.x;
    int nf = blockIdx.x & 7, mb = blockIdx.x >> 3;
    int warp = tid >> 5, lane = tid & 31;
    int gID = lane >> 2, tig = lane & 3;

    for (int i = tid; i < 128 * 256; i += 128) {
        int c = i >> 8, k = i & 255;
        ws[c * 260 + k] = g_Wc[(nf * 128 + c) * 256 + k];
    }

    // bias registers: breg[nt][ff] for col = warp*32 + nt*8 + 2*tig + ff
    float breg[4][2];
#pragma unroll
    for (int nt = 0; nt < 4; ++nt) {
        breg[nt][0] = g_bc[nf * 128 + warp * 32 + nt * 8 + 2 * tig];
        breg[nt][1] = g_bc[nf * 128 + warp * 32 + nt * 8 + 2 * tig + 1];
    }

    // cell state: e = mt*4 + rh*2 + ff -> row = mt*16 + gID + rh*8, feat j = warp*8 + 2*tig + ff
    float creg[8];
#pragma unroll
    for (int mt = 0; mt < 2; ++mt)
#pragma unroll
        for (int rh = 0; rh < 2; ++rh)
#pragma unroll
            for (int ff = 0; ff < 2; ++ff) {
                int row = mt * 16 + gID + rh * 8;
                int j = warp * 8 + 2 * tig + ff;
                creg[mt * 4 + rh * 2 + ff] = g_c1[(mb * 32 + row) * 256 + nf * 32 + j];
            }
    __syncthreads();

    for (int t = 1; t < 512; ++t) {
        if (t > 1) asm volatile("barrier.cluster.wait.aligned;" ::: "memory");

        // load h_t (32 x 256) -> smem, round to tf32
        const float* hsrc = d_out + (size_t)(t - 1) * BF + (size_t)mb * 8192;
#pragma unroll
        for (int i = tid * 4; i < 8192; i += 512) {
            float4 v = *(const float4*)(hsrc + i);
            unsigned u0, u1, u2, u3;
            asm("cvt.rna.tf32.f32 %0, %1;" : "=r"(u0) : "f"(v.x));
            asm("cvt.rna.tf32.f32 %0, %1;" : "=r"(u1) : "f"(v.y));
            asm("cvt.rna.tf32.f32 %0, %1;" : "=r"(u2) : "f"(v.z));
            asm("cvt.rna.tf32.f32 %0, %1;" : "=r"(u3) : "f"(v.w));
            v.x = __uint_as_float(u0); v.y = __uint_as_float(u1);
            v.z = __uint_as_float(u2); v.w = __uint_as_float(u3);
            *(float4*)&hs[(i >> 8) * 260 + (i & 255)] = v;
        }
        __syncthreads();

        // gates (32 x 128) = hs @ ws^T ; warp w covers cols [w*32, w*32+32), nt tile = gate nt
        float acc[2][4][4];
#pragma unroll
        for (int mt = 0; mt < 2; ++mt)
#pragma unroll
            for (int nt = 0; nt < 4; ++nt) {
                acc[mt][nt][0] = breg[nt][0]; acc[mt][nt][1] = breg[nt][1];
                acc[mt][nt][2] = breg[nt][0]; acc[mt][nt][3] = breg[nt][1];
            }

#pragma unroll 4
        for (int kb = 0; kb < 32; ++kb) {
            int k0 = kb * 8;
            unsigned a[2][4];
#pragma unroll
            for (int mt = 0; mt < 2; ++mt) {
                int r = mt * 16 + gID;
                a[mt][0] = __float_as_uint(hs[r * 260 + k0 + tig]);
                a[mt][1] = __float_as_uint(hs[(r + 8) * 260 + k0 + tig]);
                a[mt][2] = __float_as_uint(hs[r * 260 + k0 + 4 + tig]);
                a[mt][3] = __float_as_uint(hs[(r + 8) * 260 + k0 + 4 + tig]);
            }
#pragma unroll
            for (int nt = 0; nt < 4; ++nt) {
                int c = warp * 32 + nt * 8 + gID;
                unsigned b0 = __float_as_uint(ws[c * 260 + k0 + tig]);
                unsigned b1 = __float_as_uint(ws[c * 260 + k0 + 4 + tig]);
                mma8(acc[0][nt], a[0], b0, b1);
                mma8(acc[1][nt], a[1], b0, b1);
            }
        }
        __syncthreads();   // hs reads done; safe to overwrite next iteration

        // elementwise in registers + coalesced-ish float2 stores
        float* dst = d_out + (size_t)t * BF + (size_t)mb * 8192;
#pragma unroll
        for (int mt = 0; mt < 2; ++mt)
#pragma unroll
            for (int rh = 0; rh < 2; ++rh) {
                float hn2[2];
#pragma unroll
                for (int ff = 0; ff < 2; ++ff) {
                    int q = rh * 2 + ff;
                    int e = mt * 4 + rh * 2 + ff;
                    float iv = acc[mt][0][q];
                    float fv = acc[mt][1][q];
                    float gv = acc[mt][2][q];
                    float ov = acc[mt][3][q];
                    float cn = sigfast(fv) * creg[e] + sigfast(iv) * tanhfast(gv);
                    hn2[ff] = sigfast(ov) * tanhfast(cn);
                    creg[e] = cn;
                }
                int row = mt * 16 + gID + rh * 8;
                *(float2*)(dst + row * 256 + nf * 32 + warp * 8 + 2 * tig) =
                    make_float2(hn2[0], hn2[1]);
            }

        if (t < 511) asm volatile("barrier.cluster.arrive.aligned;" ::: "memory");
    }
}

extern "C" void kernel_launch(void* const* d_in, const int* in_sizes, int n_in,
                              void* d_out, int out_size) {
    const float* x   = (const float*)d_in[0];
    const float* lf  = (const float*)d_in[1];
    const float* Wi  = (const float*)d_in[2];
    const float* bi  = (const float*)d_in[3];
    const float* Wih = (const float*)d_in[4];
    const float* Whh = (const float*)d_in[5];
    const float* bih = (const float*)d_in[6];
    const float* bhh = (const float*)d_in[7];
    float* out = (float*)d_out;

    cudaFuncSetAttribute(step0_kernel, cudaFuncAttributeMaxDynamicSharedMemorySize, 98304);
    cudaFuncSetAttribute(lstm_kernel,  cudaFuncAttributeMaxDynamicSharedMemorySize, 166400);

    prep_kernel<<<1152, 256>>>(Wih, Whh, bih, bhh, Wi);
    init_kernel<<<32, 256>>>(x, bi);
    step0_kernel<<<128, 256, 98304>>>(lf, out);
    lstm_kernel<<<64, 128, 166400>>>(out);
}